// round 10
// baseline (speedup 1.0000x reference)
#include <cuda_runtime.h>
#include <cstdint>
#include <cstddef>

// Problem constants
#define TB_   128
#define NSEQ  196
#define CDIM  512
#define HDIM  2048
#define TSTEP 4
#define BB    32
#define MROWS (TB_*NSEQ)          // 25088
#define SLAB1 (NSEQ*HDIM)         // 401408
#define SLAB2 (NSEQ*CDIM)         // 100352
#define NWORD 64                  // 2048 bits per GEMM2 row

// ---------------- scratch (device globals) ---------------------------------
__device__ float    g_h1[(size_t)MROWS*HDIM];   // GEMM1 out (tb*196+n, h)
__device__ float    g_o2[(size_t)MROWS*CDIM];   // GEMM2 out (tb*196+j, c)
__device__ float    g_s2[(size_t)MROWS*CDIM];   // layer-2 spikes
__device__ uint32_t g_mask[(size_t)MROWS*NWORD]; // spike bitmask per GEMM2 row
__device__ float    g_w2T[(size_t)HDIM*CDIM];   // w2 transposed [k][c]
__device__ float    g_xT [(size_t)CDIM*MROWS];  // x transposed  [k][m]
__device__ float    g_w1T[(size_t)CDIM*HDIM];   // w1 transposed [k][h]
__device__ double   g_sum1[HDIM], g_sq1[HDIM];
__device__ double   g_sum2[CDIM], g_sq2[CDIM];
__device__ float    g_mean1[HDIM], g_rstd1[HDIM];
__device__ float    g_mean2[CDIM], g_rstd2[CDIM];

// ---------------- PTX helpers ----------------------------------------------
__device__ __forceinline__ uint32_t smem_u32(const void* p) {
    uint32_t a;
    asm("{ .reg .u64 t; cvta.to.shared.u64 t, %1; cvt.u32.u64 %0, t; }" : "=r"(a) : "l"(p));
    return a;
}
#define CP_ASYNC16(dst, src) \
    asm volatile("cp.async.cg.shared.global [%0], [%1], 16;" :: "r"(dst), "l"(src))
#define CP_COMMIT() asm volatile("cp.async.commit_group;")
#define CP_WAIT(n)  asm volatile("cp.async.wait_group %0;" :: "n"(n))

// ---------------- zero stats + mask (per launch; graph-replayable) ---------
__global__ void zero_stats_kernel() {
    int i = blockIdx.x * blockDim.x + threadIdx.x;
    if (i < HDIM) { g_sum1[i] = 0.0; g_sq1[i] = 0.0; }
    if (i < CDIM) { g_sum2[i] = 0.0; g_sq2[i] = 0.0; }
}
__global__ void zero_mask_kernel() {
    size_t i = (size_t)blockIdx.x * blockDim.x + threadIdx.x;
    if (i < (size_t)MROWS * NWORD) g_mask[i] = 0u;
}

// ---------------- generic 32x32 tile transpose: dst[c][r] = src[r][c] ------
__global__ void transpose_rc_kernel(const float* __restrict__ src,
                                    float* __restrict__ dst, int R, int C)
{
    __shared__ float t[32][33];
    int r0 = blockIdx.x * 32, c0 = blockIdx.y * 32;
    int x = threadIdx.x, y = threadIdx.y;     // block (32,8)
#pragma unroll
    for (int yy = y; yy < 32; yy += 8)
        t[yy][x] = src[(size_t)(r0 + yy) * C + c0 + x];
    __syncthreads();
#pragma unroll
    for (int yy = y; yy < 32; yy += 8)
        dst[(size_t)(c0 + yy) * R + r0 + x] = t[x][yy];
}

// ---------------- GEMM1: 3-stage cp.async ring, 1 sync/iter ----------------
// C[M,H] = x[M,512] * w1[H,512]^T, bitwise == ascending-k FMA chain.
// Inputs pre-transposed to k-major: g_xT[k][m], g_w1T[k][h].
#define BM 128
#define BN 128
#define BK 16
#define NIT (CDIM / BK)   // 32

__global__ __launch_bounds__(256, 2)
void sgemm1_kernel()
{
    __shared__ float As[3][BK][BM];   // 24 KB
    __shared__ float Bs[3][BK][BN];   // 24 KB

    const int tid = threadIdx.x;
    const int m0 = blockIdx.y * BM;
    const int n0 = blockIdx.x * BN;
    const int tx = tid & 15;
    const int ty = tid >> 4;

    float acc[8][8];
#pragma unroll
    for (int i = 0; i < 8; i++)
#pragma unroll
        for (int j = 0; j < 8; j++) acc[i][j] = 0.f;

    // chunk decomposition: 16 k-rows x 32 chunks(16B) = 512 chunks per matrix
    const int ck = tid >> 5;          // k-row (0..7; +8 for second)
    const int cc = (tid & 31) * 4;    // float offset within row

    auto load_stage = [&](int s, int k0) {
#pragma unroll
        for (int i = 0; i < 2; i++) {
            int k = ck + i * 8;
            CP_ASYNC16(smem_u32(&As[s][k][cc]),
                       g_xT + (size_t)(k0 + k) * MROWS + m0 + cc);
        }
#pragma unroll
        for (int i = 0; i < 2; i++) {
            int k = ck + i * 8;
            CP_ASYNC16(smem_u32(&Bs[s][k][cc]),
                       g_w1T + (size_t)(k0 + k) * HDIM + n0 + cc);
        }
        CP_COMMIT();
    };

    load_stage(0, 0);
    load_stage(1, BK);

    for (int it = 0; it < NIT; it++) {
        const int cur = it % 3;
        if (it + 1 < NIT) CP_WAIT(1);   // retire group `it`; group it+1 may fly
        else              CP_WAIT(0);
        __syncthreads();                // all threads see stage `cur` complete;
                                        // also proves compute(it-1) finished ->
                                        // stage (it+2)%3 reusable below

#pragma unroll
        for (int k = 0; k < BK; k++) {
            float a[8], b[8];
#pragma unroll
            for (int i = 0; i < 8; i++) a[i] = As[cur][k][ty * 8 + i];
#pragma unroll
            for (int j = 0; j < 8; j++) b[j] = Bs[cur][k][tx * 8 + j];
#pragma unroll
            for (int i = 0; i < 8; i++)
#pragma unroll
                for (int j = 0; j < 8; j++)
                    acc[i][j] = fmaf(a[i], b[j], acc[i][j]);
        }

        if (it + 2 < NIT)
            load_stage((it + 2) % 3, (it + 2) * BK);
    }

#pragma unroll
    for (int i = 0; i < 8; i++) {
        int r = m0 + ty * 8 + i;
        float* cr = g_h1 + (size_t)r * HDIM + n0 + tx * 8;
#pragma unroll
        for (int j = 0; j < 8; j += 4)
            *(float4*)(cr + j) = make_float4(acc[i][j], acc[i][j+1],
                                             acc[i][j+2], acc[i][j+3]);
    }
}

// ---------------- BN stats / final (UNCHANGED — part of passing bitstream) -
template<bool SECOND>
__global__ __launch_bounds__(256)
void bn_stats_kernel()
{
    constexpr int CH  = SECOND ? CDIM : HDIM;
    constexpr int PER = CH / 256;
    const float* __restrict__ X = SECOND ? g_o2 : g_h1;
    double* __restrict__ SUM = SECOND ? g_sum2 : g_sum1;
    double* __restrict__ SQ  = SECOND ? g_sq2  : g_sq1;

    float s[PER], q[PER];
#pragma unroll
    for (int j = 0; j < PER; j++) { s[j] = 0.f; q[j] = 0.f; }
    const int c0 = threadIdx.x;
    const float* base = X + (size_t)blockIdx.x * 128 * CH;
    for (int r = 0; r < 128; r++) {
        const float* row = base + (size_t)r * CH;
#pragma unroll
        for (int j = 0; j < PER; j++) {
            float v = row[c0 + j * 256];
            s[j] += v;
            q[j] = fmaf(v, v, q[j]);
        }
    }
#pragma unroll
    for (int j = 0; j < PER; j++) {
        atomicAdd(&SUM[c0 + j * 256], (double)s[j]);
        atomicAdd(&SQ[c0 + j * 256],  (double)q[j]);
    }
}

template<bool SECOND>
__global__ void bn_final_kernel()
{
    constexpr int CH = SECOND ? CDIM : HDIM;
    const double* SUM = SECOND ? g_sum2 : g_sum1;
    const double* SQ  = SECOND ? g_sq2  : g_sq1;
    float* MEAN = SECOND ? g_mean2 : g_mean1;
    float* RSTD = SECOND ? g_rstd2 : g_rstd1;
    int c = blockIdx.x * blockDim.x + threadIdx.x;
    if (c < CH) {
        const double inv_n = 1.0 / (double)MROWS;
        double m   = SUM[c] * inv_n;
        double var = SQ[c] * inv_n - m * m;
        MEAN[c] = (float)m;
        RSTD[c] = rsqrtf((float)var + 1e-5f);
    }
}

// ---------------- LIF layer 1 -> spike bitmask (UNCHANGED) -----------------
__global__ __launch_bounds__(256)
void lif1_kernel(const float* __restrict__ gamma, const float* __restrict__ beta)
{
    size_t tid = (size_t)blockIdx.x * blockDim.x + threadIdx.x;
    int c = (int)(tid % HDIM);
    size_t rest = tid / HDIM;
    int n = (int)(rest % NSEQ);
    int b = (int)(rest / NSEQ);

    float m  = g_mean1[c];
    float r  = g_rstd1[c];
    float gm = gamma[c];
    float bt = beta[c];

    int f = n * HDIM + c;
    int k = f / NSEQ;
    int j = f - k * NSEQ;
    uint32_t bit  = 1u << (k & 31);
    int      word = k >> 5;

    float v = 0.f;
#pragma unroll
    for (int t = 0; t < TSTEP; t++) {
        int tb = t * BB + b;
        float x  = g_h1[((size_t)tb * NSEQ + n) * HDIM + c];
        float xn = __fadd_rn(__fmul_rn(__fmul_rn(gm, __fsub_rn(x, m)), r), bt);
        v = __fadd_rn(v, __fmul_rn(__fsub_rn(xn, v), 0.5f));
        if (v >= 1.0f) {
            atomicOr(&g_mask[(size_t)(tb * NSEQ + j) * NWORD + word], bit);
            v = 0.f;
        }
    }
}

// ---------------- sparse GEMM2: o2[r][c] = sum_{k active} w2T[k][c] --------
// Bitwise == reference (ascending-k FADD chain); loads batched MLP=8.
#define RPC 8
__global__ __launch_bounds__(512)
void gemm2_sparse_kernel()
{
    __shared__ uint32_t wbits[NWORD];
    __shared__ uint16_t klist[HDIM];
    __shared__ uint16_t excl[NWORD];
    __shared__ int warpsum[2];
    __shared__ int s_knum;

    const int tid = threadIdx.x;     // c = tid (0..511)
    const int row0 = blockIdx.x * RPC;

    for (int rr = 0; rr < RPC; rr++) {
        const int row = row0 + rr;
        if (tid < NWORD) wbits[tid] = g_mask[(size_t)row * NWORD + tid];
        __syncthreads();

        if (tid < NWORD) {
            uint32_t mw = wbits[tid];
            int cnt = __popc(mw);
            int incl = cnt;
#pragma unroll
            for (int d = 1; d < 32; d <<= 1) {
                int vv = __shfl_up_sync(0xffffffffu, incl, d);
                if ((tid & 31) >= d) incl += vv;
            }
            excl[tid] = (uint16_t)(incl - cnt);
            if ((tid & 31) == 31) warpsum[tid >> 5] = incl;
        }
        __syncthreads();

        if (tid < NWORD) {
            int off = excl[tid] + ((tid >= 32) ? warpsum[0] : 0);
            uint32_t mw = wbits[tid];
            int kb = tid * 32;
            while (mw) {
                int b = __ffs(mw) - 1;
                mw &= mw - 1;
                klist[off++] = (uint16_t)(kb + b);
            }
            if (tid == 63) s_knum = warpsum[0] + warpsum[1];
        }
        __syncthreads();

        const int knum = s_knum;
        float acc = 0.f;
        int i = 0;
        for (; i + 8 <= knum; i += 8) {
            float v0 = g_w2T[(size_t)klist[i+0] * CDIM + tid];
            float v1 = g_w2T[(size_t)klist[i+1] * CDIM + tid];
            float v2 = g_w2T[(size_t)klist[i+2] * CDIM + tid];
            float v3 = g_w2T[(size_t)klist[i+3] * CDIM + tid];
            float v4 = g_w2T[(size_t)klist[i+4] * CDIM + tid];
            float v5 = g_w2T[(size_t)klist[i+5] * CDIM + tid];
            float v6 = g_w2T[(size_t)klist[i+6] * CDIM + tid];
            float v7 = g_w2T[(size_t)klist[i+7] * CDIM + tid];
            acc = __fadd_rn(acc, v0);
            acc = __fadd_rn(acc, v1);
            acc = __fadd_rn(acc, v2);
            acc = __fadd_rn(acc, v3);
            acc = __fadd_rn(acc, v4);
            acc = __fadd_rn(acc, v5);
            acc = __fadd_rn(acc, v6);
            acc = __fadd_rn(acc, v7);
        }
        for (; i < knum; i++)
            acc = __fadd_rn(acc, g_w2T[(size_t)klist[i] * CDIM + tid]);

        g_o2[(size_t)row * CDIM + tid] = acc;
        __syncthreads();
    }
}

// ---------------- LIF layer 2 (UNCHANGED) ----------------------------------
__global__ __launch_bounds__(256)
void lif2_kernel(const float* __restrict__ gamma, const float* __restrict__ beta)
{
    size_t tid = (size_t)blockIdx.x * blockDim.x + threadIdx.x;
    int c = (int)(tid % CDIM);
    size_t rest = tid / CDIM;
    int n = (int)(rest % NSEQ);
    int b = (int)(rest / NSEQ);

    float m  = g_mean2[c];
    float r  = g_rstd2[c];
    float gm = gamma[c];
    float bt = beta[c];

    float v = 0.f;
#pragma unroll
    for (int t = 0; t < TSTEP; t++) {
        size_t tb = (size_t)(t * BB + b);
        float x  = g_o2[(tb * NSEQ + n) * CDIM + c];
        float xn = __fadd_rn(__fmul_rn(__fmul_rn(gm, __fsub_rn(x, m)), r), bt);
        v = __fadd_rn(v, __fmul_rn(__fsub_rn(xn, v), 0.5f));
        float sp = (v >= 1.0f) ? 1.0f : 0.0f;
        g_s2[tb * SLAB2 + (size_t)n * CDIM + c] = sp;
        if (v >= 1.0f) v = 0.f;
    }
}

// ---------------- final permuted write -------------------------------------
__global__ void transpose_out_kernel(float* __restrict__ out)
{
    __shared__ float tile[32][33];
    int tb = blockIdx.z;
    int i0 = blockIdx.y * 32;
    int j0 = blockIdx.x * 32;
    const float* src = g_s2 + (size_t)tb * SLAB2;
    float* dst = out + (size_t)tb * SLAB2;
    int x = threadIdx.x, y = threadIdx.y;

#pragma unroll
    for (int yy = y; yy < 32; yy += 8) {
        int i = i0 + yy, j = j0 + x;
        if (j < NSEQ) tile[yy][x] = src[(size_t)i * NSEQ + j];
    }
    __syncthreads();
#pragma unroll
    for (int yy = y; yy < 32; yy += 8) {
        int j = j0 + yy, i = i0 + x;
        if (j < NSEQ) dst[(size_t)j * CDIM + i] = tile[x][yy];
    }
}

// ---------------- launch ----------------------------------------------------
extern "C" void kernel_launch(void* const* d_in, const int* in_sizes, int n_in,
                              void* d_out, int out_size)
{
    const float* x  = (const float*)d_in[0];
    const float* w1 = (const float*)d_in[1];
    const float* g1 = (const float*)d_in[2];
    const float* b1 = (const float*)d_in[3];
    const float* w2 = (const float*)d_in[4];
    const float* g2 = (const float*)d_in[5];
    const float* b2 = (const float*)d_in[6];
    float* out = (float*)d_out;

    // Resolve device-global addresses for the generic transpose
    float *p_xT, *p_w1T, *p_w2T;
    cudaGetSymbolAddress((void**)&p_xT,  g_xT);
    cudaGetSymbolAddress((void**)&p_w1T, g_w1T);
    cudaGetSymbolAddress((void**)&p_w2T, g_w2T);

    zero_stats_kernel<<<8, 256>>>();
    zero_mask_kernel<<<((size_t)MROWS * NWORD + 1023) / 1024, 1024>>>();

    // Pre-transposes: x[25088][512]->xT, w1[2048][512]->w1T, w2[512][2048]->w2T
    transpose_rc_kernel<<<dim3(MROWS / 32, CDIM / 32), dim3(32, 8)>>>(x,  p_xT,  MROWS, CDIM);
    transpose_rc_kernel<<<dim3(HDIM / 32, CDIM / 32), dim3(32, 8)>>>(w1, p_w1T, HDIM, CDIM);
    transpose_rc_kernel<<<dim3(CDIM / 32, HDIM / 32), dim3(32, 8)>>>(w2, p_w2T, CDIM, HDIM);

    // Layer 1: 3-stage pipelined fp32 GEMM (bitwise chain) -> g_h1
    sgemm1_kernel<<<dim3(HDIM / BN, MROWS / BM), 256>>>();
    bn_stats_kernel<false><<<MROWS / 128, 256>>>();
    bn_final_kernel<false><<<HDIM / 256, 256>>>();
    lif1_kernel<<<((size_t)BB * NSEQ * HDIM) / 256, 256>>>(g1, b1);

    // Layer 2: sparse spike GEMM (exact no-op elision) -> g_o2
    gemm2_sparse_kernel<<<MROWS / RPC, 512>>>();
    bn_stats_kernel<true><<<MROWS / 128, 256>>>();
    bn_final_kernel<true><<<CDIM / 256, 256>>>();
    lif2_kernel<<<((size_t)BB * NSEQ * CDIM) / 256, 256>>>(g2, b2);

    transpose_out_kernel<<<dim3(7, CDIM / 32, TB_), dim3(32, 8)>>>(out);
}

// round 11
// speedup vs baseline: 1.0347x; 1.0347x over previous
#include <cuda_runtime.h>
#include <cstdint>
#include <cstddef>

// Problem constants
#define TB_   128
#define NSEQ  196
#define CDIM  512
#define HDIM  2048
#define TSTEP 4
#define BB    32
#define MROWS (TB_*NSEQ)          // 25088
#define SLAB1 (NSEQ*HDIM)         // 401408
#define SLAB2 (NSEQ*CDIM)         // 100352
#define NWORD 64                  // 2048 bits per GEMM2 row

// ---------------- scratch (device globals) ---------------------------------
__device__ float    g_h1[(size_t)MROWS*HDIM];   // GEMM1 out (tb*196+n, h)
__device__ float    g_o2[(size_t)MROWS*CDIM];   // GEMM2 out (tb*196+j, c)
__device__ float    g_s2[(size_t)MROWS*CDIM];   // layer-2 spikes
__device__ uint32_t g_mask[(size_t)MROWS*NWORD]; // spike bitmask per GEMM2 row
__device__ float    g_w2T[(size_t)HDIM*CDIM];   // w2 transposed [k][c]
__device__ float    g_xT [(size_t)CDIM*MROWS];  // x transposed  [k][m]
__device__ float    g_w1T[(size_t)CDIM*HDIM];   // w1 transposed [k][h]
__device__ double   g_sum1[HDIM], g_sq1[HDIM];
__device__ double   g_sum2[CDIM], g_sq2[CDIM];
__device__ float    g_mean1[HDIM], g_rstd1[HDIM];
__device__ float    g_mean2[CDIM], g_rstd2[CDIM];

// ---------------- PTX helpers ----------------------------------------------
__device__ __forceinline__ uint32_t smem_u32(const void* p) {
    uint32_t a;
    asm("{ .reg .u64 t; cvta.to.shared.u64 t, %1; cvt.u32.u64 %0, t; }" : "=r"(a) : "l"(p));
    return a;
}
#define CP_ASYNC16(dst, src) \
    asm volatile("cp.async.cg.shared.global [%0], [%1], 16;" :: "r"(dst), "l"(src))
#define CP_COMMIT() asm volatile("cp.async.commit_group;")
#define CP_WAIT(n)  asm volatile("cp.async.wait_group %0;" :: "n"(n))

__device__ __forceinline__ void ffma2(unsigned long long &d,
                                      unsigned long long a,
                                      unsigned long long b)
{
    asm("fma.rn.f32x2 %0, %1, %2, %3;" : "=l"(d) : "l"(a), "l"(b), "l"(d));
}
__device__ __forceinline__ unsigned long long dup2(float v)
{
    unsigned long long r;
    asm("mov.b64 %0, {%1, %1};" : "=l"(r) : "f"(v));
    return r;
}

// ---------------- zero stats + mask (per launch; graph-replayable) ---------
__global__ void zero_stats_kernel() {
    int i = blockIdx.x * blockDim.x + threadIdx.x;
    if (i < HDIM) { g_sum1[i] = 0.0; g_sq1[i] = 0.0; }
    if (i < CDIM) { g_sum2[i] = 0.0; g_sq2[i] = 0.0; }
}
__global__ void zero_mask_kernel() {
    size_t i = (size_t)blockIdx.x * blockDim.x + threadIdx.x;
    if (i < (size_t)MROWS * NWORD) g_mask[i] = 0u;
}

// ---------------- generic 32x32 tile transpose: dst[c][r] = src[r][c] ------
__global__ void transpose_rc_kernel(const float* __restrict__ src,
                                    float* __restrict__ dst, int R, int C)
{
    __shared__ float t[32][33];
    int r0 = blockIdx.x * 32, c0 = blockIdx.y * 32;
    int x = threadIdx.x, y = threadIdx.y;     // block (32,8)
#pragma unroll
    for (int yy = y; yy < 32; yy += 8)
        t[yy][x] = src[(size_t)(r0 + yy) * C + c0 + x];
    __syncthreads();
#pragma unroll
    for (int yy = y; yy < 32; yy += 8)
        dst[(size_t)(c0 + yy) * R + r0 + x] = t[x][yy];
}

// ---------------- GEMM1: 3-stage cp.async ring + packed f32x2 FMA ----------
// C[M,H] = x[M,512] * w1[H,512]^T, bitwise == ascending-k FMA chain
// (each f32x2 lane is an independent RN FMA; chain order unchanged).
// Inputs pre-transposed to k-major: g_xT[k][m], g_w1T[k][h].
#define BM 128
#define BN 128
#define BK 16
#define NIT (CDIM / BK)   // 32

__global__ __launch_bounds__(256, 2)
void sgemm1_kernel()
{
    __shared__ __align__(16) float As[3][BK][BM];   // 24 KB
    __shared__ __align__(16) float Bs[3][BK][BN];   // 24 KB

    const int tid = threadIdx.x;
    const int m0 = blockIdx.y * BM;
    const int n0 = blockIdx.x * BN;
    const int tx = tid & 15;
    const int ty = tid >> 4;

    unsigned long long acc[8][4];   // 8 m-rows x 4 n-pairs (2 floats each)
#pragma unroll
    for (int i = 0; i < 8; i++)
#pragma unroll
        for (int p = 0; p < 4; p++) acc[i][p] = 0ull;

    // chunk decomposition: 16 k-rows x 32 chunks(16B) = 512 chunks per matrix
    const int ck = tid >> 5;          // k-row (0..7; +8 for second)
    const int cc = (tid & 31) * 4;    // float offset within row

    auto load_stage = [&](int s, int k0) {
#pragma unroll
        for (int i = 0; i < 2; i++) {
            int k = ck + i * 8;
            CP_ASYNC16(smem_u32(&As[s][k][cc]),
                       g_xT + (size_t)(k0 + k) * MROWS + m0 + cc);
        }
#pragma unroll
        for (int i = 0; i < 2; i++) {
            int k = ck + i * 8;
            CP_ASYNC16(smem_u32(&Bs[s][k][cc]),
                       g_w1T + (size_t)(k0 + k) * HDIM + n0 + cc);
        }
        CP_COMMIT();
    };

    load_stage(0, 0);
    load_stage(1, BK);

    for (int it = 0; it < NIT; it++) {
        const int cur = it % 3;
        if (it + 1 < NIT) CP_WAIT(1);
        else              CP_WAIT(0);
        __syncthreads();

#pragma unroll
        for (int k = 0; k < BK; k++) {
            // A fragment: 8 scalars (2x LDS.128), dup to {a,a} pairs
            float4 af0 = *(const float4*)&As[cur][k][ty * 8];
            float4 af1 = *(const float4*)&As[cur][k][ty * 8 + 4];
            unsigned long long a2[8];
            a2[0] = dup2(af0.x); a2[1] = dup2(af0.y);
            a2[2] = dup2(af0.z); a2[3] = dup2(af0.w);
            a2[4] = dup2(af1.x); a2[5] = dup2(af1.y);
            a2[6] = dup2(af1.z); a2[7] = dup2(af1.w);
            // B fragment: 8 consecutive n-floats = 4 natural pairs
            ulonglong2 bq0 = *(const ulonglong2*)&Bs[cur][k][tx * 8];
            ulonglong2 bq1 = *(const ulonglong2*)&Bs[cur][k][tx * 8 + 4];
            unsigned long long b2[4] = {bq0.x, bq0.y, bq1.x, bq1.y};
#pragma unroll
            for (int i = 0; i < 8; i++)
#pragma unroll
                for (int p = 0; p < 4; p++)
                    ffma2(acc[i][p], a2[i], b2[p]);
        }

        if (it + 2 < NIT)
            load_stage((it + 2) % 3, (it + 2) * BK);
    }

#pragma unroll
    for (int i = 0; i < 8; i++) {
        int r = m0 + ty * 8 + i;
        float* cr = g_h1 + (size_t)r * HDIM + n0 + tx * 8;
        ulonglong2 v0; v0.x = acc[i][0]; v0.y = acc[i][1];
        ulonglong2 v1; v1.x = acc[i][2]; v1.y = acc[i][3];
        *(ulonglong2*)(cr)     = v0;
        *(ulonglong2*)(cr + 4) = v1;
    }
}

// ---------------- BN stats / final (UNCHANGED — part of passing bitstream) -
template<bool SECOND>
__global__ __launch_bounds__(256)
void bn_stats_kernel()
{
    constexpr int CH  = SECOND ? CDIM : HDIM;
    constexpr int PER = CH / 256;
    const float* __restrict__ X = SECOND ? g_o2 : g_h1;
    double* __restrict__ SUM = SECOND ? g_sum2 : g_sum1;
    double* __restrict__ SQ  = SECOND ? g_sq2  : g_sq1;

    float s[PER], q[PER];
#pragma unroll
    for (int j = 0; j < PER; j++) { s[j] = 0.f; q[j] = 0.f; }
    const int c0 = threadIdx.x;
    const float* base = X + (size_t)blockIdx.x * 128 * CH;
    for (int r = 0; r < 128; r++) {
        const float* row = base + (size_t)r * CH;
#pragma unroll
        for (int j = 0; j < PER; j++) {
            float v = row[c0 + j * 256];
            s[j] += v;
            q[j] = fmaf(v, v, q[j]);
        }
    }
#pragma unroll
    for (int j = 0; j < PER; j++) {
        atomicAdd(&SUM[c0 + j * 256], (double)s[j]);
        atomicAdd(&SQ[c0 + j * 256],  (double)q[j]);
    }
}

template<bool SECOND>
__global__ void bn_final_kernel()
{
    constexpr int CH = SECOND ? CDIM : HDIM;
    const double* SUM = SECOND ? g_sum2 : g_sum1;
    const double* SQ  = SECOND ? g_sq2  : g_sq1;
    float* MEAN = SECOND ? g_mean2 : g_mean1;
    float* RSTD = SECOND ? g_rstd2 : g_rstd1;
    int c = blockIdx.x * blockDim.x + threadIdx.x;
    if (c < CH) {
        const double inv_n = 1.0 / (double)MROWS;
        double m   = SUM[c] * inv_n;
        double var = SQ[c] * inv_n - m * m;
        MEAN[c] = (float)m;
        RSTD[c] = rsqrtf((float)var + 1e-5f);
    }
}

// ---------------- LIF layer 1 -> spike bitmask (UNCHANGED) -----------------
__global__ __launch_bounds__(256)
void lif1_kernel(const float* __restrict__ gamma, const float* __restrict__ beta)
{
    size_t tid = (size_t)blockIdx.x * blockDim.x + threadIdx.x;
    int c = (int)(tid % HDIM);
    size_t rest = tid / HDIM;
    int n = (int)(rest % NSEQ);
    int b = (int)(rest / NSEQ);

    float m  = g_mean1[c];
    float r  = g_rstd1[c];
    float gm = gamma[c];
    float bt = beta[c];

    int f = n * HDIM + c;
    int k = f / NSEQ;
    int j = f - k * NSEQ;
    uint32_t bit  = 1u << (k & 31);
    int      word = k >> 5;

    float v = 0.f;
#pragma unroll
    for (int t = 0; t < TSTEP; t++) {
        int tb = t * BB + b;
        float x  = g_h1[((size_t)tb * NSEQ + n) * HDIM + c];
        float xn = __fadd_rn(__fmul_rn(__fmul_rn(gm, __fsub_rn(x, m)), r), bt);
        v = __fadd_rn(v, __fmul_rn(__fsub_rn(xn, v), 0.5f));
        if (v >= 1.0f) {
            atomicOr(&g_mask[(size_t)(tb * NSEQ + j) * NWORD + word], bit);
            v = 0.f;
        }
    }
}

// ---------------- sparse GEMM2: o2[r][c] = sum_{k active} w2T[k][c] --------
// Bitwise == reference (ascending-k FADD chain); loads batched MLP=8.
#define RPC 8
__global__ __launch_bounds__(512)
void gemm2_sparse_kernel()
{
    __shared__ uint32_t wbits[NWORD];
    __shared__ uint16_t klist[HDIM];
    __shared__ uint16_t excl[NWORD];
    __shared__ int warpsum[2];
    __shared__ int s_knum;

    const int tid = threadIdx.x;     // c = tid (0..511)
    const int row0 = blockIdx.x * RPC;

    for (int rr = 0; rr < RPC; rr++) {
        const int row = row0 + rr;
        if (tid < NWORD) wbits[tid] = g_mask[(size_t)row * NWORD + tid];
        __syncthreads();

        if (tid < NWORD) {
            uint32_t mw = wbits[tid];
            int cnt = __popc(mw);
            int incl = cnt;
#pragma unroll
            for (int d = 1; d < 32; d <<= 1) {
                int vv = __shfl_up_sync(0xffffffffu, incl, d);
                if ((tid & 31) >= d) incl += vv;
            }
            excl[tid] = (uint16_t)(incl - cnt);
            if ((tid & 31) == 31) warpsum[tid >> 5] = incl;
        }
        __syncthreads();

        if (tid < NWORD) {
            int off = excl[tid] + ((tid >= 32) ? warpsum[0] : 0);
            uint32_t mw = wbits[tid];
            int kb = tid * 32;
            while (mw) {
                int b = __ffs(mw) - 1;
                mw &= mw - 1;
                klist[off++] = (uint16_t)(kb + b);
            }
            if (tid == 63) s_knum = warpsum[0] + warpsum[1];
        }
        __syncthreads();

        const int knum = s_knum;
        float acc = 0.f;
        int i = 0;
        for (; i + 8 <= knum; i += 8) {
            float v0 = g_w2T[(size_t)klist[i+0] * CDIM + tid];
            float v1 = g_w2T[(size_t)klist[i+1] * CDIM + tid];
            float v2 = g_w2T[(size_t)klist[i+2] * CDIM + tid];
            float v3 = g_w2T[(size_t)klist[i+3] * CDIM + tid];
            float v4 = g_w2T[(size_t)klist[i+4] * CDIM + tid];
            float v5 = g_w2T[(size_t)klist[i+5] * CDIM + tid];
            float v6 = g_w2T[(size_t)klist[i+6] * CDIM + tid];
            float v7 = g_w2T[(size_t)klist[i+7] * CDIM + tid];
            acc = __fadd_rn(acc, v0);
            acc = __fadd_rn(acc, v1);
            acc = __fadd_rn(acc, v2);
            acc = __fadd_rn(acc, v3);
            acc = __fadd_rn(acc, v4);
            acc = __fadd_rn(acc, v5);
            acc = __fadd_rn(acc, v6);
            acc = __fadd_rn(acc, v7);
        }
        for (; i < knum; i++)
            acc = __fadd_rn(acc, g_w2T[(size_t)klist[i] * CDIM + tid]);

        g_o2[(size_t)row * CDIM + tid] = acc;
        __syncthreads();
    }
}

// ---------------- LIF layer 2 (UNCHANGED) ----------------------------------
__global__ __launch_bounds__(256)
void lif2_kernel(const float* __restrict__ gamma, const float* __restrict__ beta)
{
    size_t tid = (size_t)blockIdx.x * blockDim.x + threadIdx.x;
    int c = (int)(tid % CDIM);
    size_t rest = tid / CDIM;
    int n = (int)(rest % NSEQ);
    int b = (int)(rest / NSEQ);

    float m  = g_mean2[c];
    float r  = g_rstd2[c];
    float gm = gamma[c];
    float bt = beta[c];

    float v = 0.f;
#pragma unroll
    for (int t = 0; t < TSTEP; t++) {
        size_t tb = (size_t)(t * BB + b);
        float x  = g_o2[(tb * NSEQ + n) * CDIM + c];
        float xn = __fadd_rn(__fmul_rn(__fmul_rn(gm, __fsub_rn(x, m)), r), bt);
        v = __fadd_rn(v, __fmul_rn(__fsub_rn(xn, v), 0.5f));
        float sp = (v >= 1.0f) ? 1.0f : 0.0f;
        g_s2[tb * SLAB2 + (size_t)n * CDIM + c] = sp;
        if (v >= 1.0f) v = 0.f;
    }
}

// ---------------- final permuted write -------------------------------------
__global__ void transpose_out_kernel(float* __restrict__ out)
{
    __shared__ float tile[32][33];
    int tb = blockIdx.z;
    int i0 = blockIdx.y * 32;
    int j0 = blockIdx.x * 32;
    const float* src = g_s2 + (size_t)tb * SLAB2;
    float* dst = out + (size_t)tb * SLAB2;
    int x = threadIdx.x, y = threadIdx.y;

#pragma unroll
    for (int yy = y; yy < 32; yy += 8) {
        int i = i0 + yy, j = j0 + x;
        if (j < NSEQ) tile[yy][x] = src[(size_t)i * NSEQ + j];
    }
    __syncthreads();
#pragma unroll
    for (int yy = y; yy < 32; yy += 8) {
        int j = j0 + yy, i = i0 + x;
        if (j < NSEQ) dst[(size_t)j * CDIM + i] = tile[x][yy];
    }
}

// ---------------- launch ----------------------------------------------------
extern "C" void kernel_launch(void* const* d_in, const int* in_sizes, int n_in,
                              void* d_out, int out_size)
{
    const float* x  = (const float*)d_in[0];
    const float* w1 = (const float*)d_in[1];
    const float* g1 = (const float*)d_in[2];
    const float* b1 = (const float*)d_in[3];
    const float* w2 = (const float*)d_in[4];
    const float* g2 = (const float*)d_in[5];
    const float* b2 = (const float*)d_in[6];
    float* out = (float*)d_out;

    // Resolve device-global addresses for the generic transpose
    float *p_xT, *p_w1T, *p_w2T;
    cudaGetSymbolAddress((void**)&p_xT,  g_xT);
    cudaGetSymbolAddress((void**)&p_w1T, g_w1T);
    cudaGetSymbolAddress((void**)&p_w2T, g_w2T);

    zero_stats_kernel<<<8, 256>>>();
    zero_mask_kernel<<<((size_t)MROWS * NWORD + 1023) / 1024, 1024>>>();

    // Pre-transposes: x[25088][512]->xT, w1[2048][512]->w1T, w2[512][2048]->w2T
    transpose_rc_kernel<<<dim3(MROWS / 32, CDIM / 32), dim3(32, 8)>>>(x,  p_xT,  MROWS, CDIM);
    transpose_rc_kernel<<<dim3(HDIM / 32, CDIM / 32), dim3(32, 8)>>>(w1, p_w1T, HDIM, CDIM);
    transpose_rc_kernel<<<dim3(CDIM / 32, HDIM / 32), dim3(32, 8)>>>(w2, p_w2T, CDIM, HDIM);

    // Layer 1: pipelined f32x2 GEMM (bitwise chain) -> g_h1
    sgemm1_kernel<<<dim3(HDIM / BN, MROWS / BM), 256>>>();
    bn_stats_kernel<false><<<MROWS / 128, 256>>>();
    bn_final_kernel<false><<<HDIM / 256, 256>>>();
    lif1_kernel<<<((size_t)BB * NSEQ * HDIM) / 256, 256>>>(g1, b1);

    // Layer 2: sparse spike GEMM (exact no-op elision) -> g_o2
    gemm2_sparse_kernel<<<MROWS / RPC, 512>>>();
    bn_stats_kernel<true><<<MROWS / 128, 256>>>();
    bn_final_kernel<true><<<CDIM / 256, 256>>>();
    lif2_kernel<<<((size_t)BB * NSEQ * CDIM) / 256, 256>>>(g2, b2);

    transpose_out_kernel<<<dim3(7, CDIM / 32, TB_), dim3(32, 8)>>>(out);
}

// round 14
// speedup vs baseline: 1.0924x; 1.0557x over previous
#include <cuda_runtime.h>
#include <cstdint>
#include <cstddef>

// Problem constants
#define TB_   128
#define NSEQ  196
#define CDIM  512
#define HDIM  2048
#define TSTEP 4
#define BB    32
#define MROWS (TB_*NSEQ)          // 25088
#define SLAB1 (NSEQ*HDIM)         // 401408
#define SLAB2 (NSEQ*CDIM)         // 100352
#define NWORD 64                  // 2048 bits per GEMM2 row

// ---------------- scratch (device globals) ---------------------------------
__device__ float    g_h1[(size_t)MROWS*HDIM];   // GEMM1 out (tb*196+n, h)
__device__ float    g_o2[(size_t)MROWS*CDIM];   // GEMM2 out (tb*196+j, c)
__device__ float    g_s2[(size_t)MROWS*CDIM];   // layer-2 spikes
__device__ uint32_t g_mask[(size_t)MROWS*NWORD]; // spike bitmask per GEMM2 row
__device__ float    g_w2T[(size_t)HDIM*CDIM];   // w2 transposed [k][c]
__device__ float    g_xT [(size_t)CDIM*MROWS];  // x transposed  [k][m]
__device__ float    g_w1T[(size_t)CDIM*HDIM];   // w1 transposed [k][h]
__device__ double   g_sum1[HDIM], g_sq1[HDIM];
__device__ double   g_sum2[CDIM], g_sq2[CDIM];
__device__ float    g_mean1[HDIM], g_rstd1[HDIM];
__device__ float    g_mean2[CDIM], g_rstd2[CDIM];

// ---------------- PTX helpers ----------------------------------------------
__device__ __forceinline__ uint32_t smem_u32(const void* p) {
    uint32_t a;
    asm("{ .reg .u64 t; cvta.to.shared.u64 t, %1; cvt.u32.u64 %0, t; }" : "=r"(a) : "l"(p));
    return a;
}
#define CP_ASYNC16(dst, src) \
    asm volatile("cp.async.cg.shared.global [%0], [%1], 16;" :: "r"(dst), "l"(src))
#define CP_COMMIT() asm volatile("cp.async.commit_group;")
#define CP_WAIT(n)  asm volatile("cp.async.wait_group %0;" :: "n"(n))

__device__ __forceinline__ void ffma2(unsigned long long &d,
                                      unsigned long long a,
                                      unsigned long long b)
{
    asm("fma.rn.f32x2 %0, %1, %2, %3;" : "=l"(d) : "l"(a), "l"(b), "l"(d));
}
__device__ __forceinline__ unsigned long long dup2(float v)
{
    unsigned long long r;
    asm("mov.b64 %0, {%1, %1};" : "=l"(r) : "f"(v));
    return r;
}

// ---------------- zero stats + mask (per launch; graph-replayable) ---------
__global__ void zero_stats_kernel() {
    int i = blockIdx.x * blockDim.x + threadIdx.x;
    if (i < HDIM) { g_sum1[i] = 0.0; g_sq1[i] = 0.0; }
    if (i < CDIM) { g_sum2[i] = 0.0; g_sq2[i] = 0.0; }
}
__global__ void zero_mask_kernel() {
    size_t i = (size_t)blockIdx.x * blockDim.x + threadIdx.x;
    if (i < (size_t)MROWS * NWORD) g_mask[i] = 0u;
}

// ---------------- generic 32x32 tile transpose: dst[c][r] = src[r][c] ------
__global__ void transpose_rc_kernel(const float* __restrict__ src,
                                    float* __restrict__ dst, int R, int C)
{
    __shared__ float t[32][33];
    int r0 = blockIdx.x * 32, c0 = blockIdx.y * 32;
    int x = threadIdx.x, y = threadIdx.y;     // block (32,8)
#pragma unroll
    for (int yy = y; yy < 32; yy += 8)
        t[yy][x] = src[(size_t)(r0 + yy) * C + c0 + x];
    __syncthreads();
#pragma unroll
    for (int yy = y; yy < 32; yy += 8)
        dst[(size_t)(c0 + yy) * R + r0 + x] = t[x][yy];
}

// ---------------- GEMM1: 3-stage cp.async ring + packed f32x2 FMA ----------
// C[M,H] = x[M,512] * w1[H,512]^T, bitwise == ascending-k FMA chain.
// Inputs pre-transposed to k-major: g_xT[k][m], g_w1T[k][h].
#define BM 128
#define BN 128
#define BK 16
#define NIT (CDIM / BK)   // 32

__global__ __launch_bounds__(256, 2)
void sgemm1_kernel()
{
    __shared__ __align__(16) float As[3][BK][BM];   // 24 KB
    __shared__ __align__(16) float Bs[3][BK][BN];   // 24 KB

    const int tid = threadIdx.x;
    const int m0 = blockIdx.y * BM;
    const int n0 = blockIdx.x * BN;
    const int tx = tid & 15;
    const int ty = tid >> 4;

    unsigned long long acc[8][4];
#pragma unroll
    for (int i = 0; i < 8; i++)
#pragma unroll
        for (int p = 0; p < 4; p++) acc[i][p] = 0ull;

    const int ck = tid >> 5;
    const int cc = (tid & 31) * 4;

    auto load_stage = [&](int s, int k0) {
#pragma unroll
        for (int i = 0; i < 2; i++) {
            int k = ck + i * 8;
            CP_ASYNC16(smem_u32(&As[s][k][cc]),
                       g_xT + (size_t)(k0 + k) * MROWS + m0 + cc);
        }
#pragma unroll
        for (int i = 0; i < 2; i++) {
            int k = ck + i * 8;
            CP_ASYNC16(smem_u32(&Bs[s][k][cc]),
                       g_w1T + (size_t)(k0 + k) * HDIM + n0 + cc);
        }
        CP_COMMIT();
    };

    load_stage(0, 0);
    load_stage(1, BK);

    for (int it = 0; it < NIT; it++) {
        const int cur = it % 3;
        if (it + 1 < NIT) CP_WAIT(1);
        else              CP_WAIT(0);
        __syncthreads();

#pragma unroll
        for (int k = 0; k < BK; k++) {
            float4 af0 = *(const float4*)&As[cur][k][ty * 8];
            float4 af1 = *(const float4*)&As[cur][k][ty * 8 + 4];
            unsigned long long a2[8];
            a2[0] = dup2(af0.x); a2[1] = dup2(af0.y);
            a2[2] = dup2(af0.z); a2[3] = dup2(af0.w);
            a2[4] = dup2(af1.x); a2[5] = dup2(af1.y);
            a2[6] = dup2(af1.z); a2[7] = dup2(af1.w);
            ulonglong2 bq0 = *(const ulonglong2*)&Bs[cur][k][tx * 8];
            ulonglong2 bq1 = *(const ulonglong2*)&Bs[cur][k][tx * 8 + 4];
            unsigned long long b2[4] = {bq0.x, bq0.y, bq1.x, bq1.y};
#pragma unroll
            for (int i = 0; i < 8; i++)
#pragma unroll
                for (int p = 0; p < 4; p++)
                    ffma2(acc[i][p], a2[i], b2[p]);
        }

        if (it + 2 < NIT)
            load_stage((it + 2) % 3, (it + 2) * BK);
    }

#pragma unroll
    for (int i = 0; i < 8; i++) {
        int r = m0 + ty * 8 + i;
        float* cr = g_h1 + (size_t)r * HDIM + n0 + tx * 8;
        ulonglong2 v0; v0.x = acc[i][0]; v0.y = acc[i][1];
        ulonglong2 v1; v1.x = acc[i][2]; v1.y = acc[i][3];
        *(ulonglong2*)(cr)     = v0;
        *(ulonglong2*)(cr + 4) = v1;
    }
}

// ---------------- BN stats / final (UNCHANGED — part of passing bitstream) -
template<bool SECOND>
__global__ __launch_bounds__(256)
void bn_stats_kernel()
{
    constexpr int CH  = SECOND ? CDIM : HDIM;
    constexpr int PER = CH / 256;
    const float* __restrict__ X = SECOND ? g_o2 : g_h1;
    double* __restrict__ SUM = SECOND ? g_sum2 : g_sum1;
    double* __restrict__ SQ  = SECOND ? g_sq2  : g_sq1;

    float s[PER], q[PER];
#pragma unroll
    for (int j = 0; j < PER; j++) { s[j] = 0.f; q[j] = 0.f; }
    const int c0 = threadIdx.x;
    const float* base = X + (size_t)blockIdx.x * 128 * CH;
    for (int r = 0; r < 128; r++) {
        const float* row = base + (size_t)r * CH;
#pragma unroll
        for (int j = 0; j < PER; j++) {
            float v = row[c0 + j * 256];
            s[j] += v;
            q[j] = fmaf(v, v, q[j]);
        }
    }
#pragma unroll
    for (int j = 0; j < PER; j++) {
        atomicAdd(&SUM[c0 + j * 256], (double)s[j]);
        atomicAdd(&SQ[c0 + j * 256],  (double)q[j]);
    }
}

template<bool SECOND>
__global__ void bn_final_kernel()
{
    constexpr int CH = SECOND ? CDIM : HDIM;
    const double* SUM = SECOND ? g_sum2 : g_sum1;
    const double* SQ  = SECOND ? g_sq2  : g_sq1;
    float* MEAN = SECOND ? g_mean2 : g_mean1;
    float* RSTD = SECOND ? g_rstd2 : g_rstd1;
    int c = blockIdx.x * blockDim.x + threadIdx.x;
    if (c < CH) {
        const double inv_n = 1.0 / (double)MROWS;
        double m   = SUM[c] * inv_n;
        double var = SQ[c] * inv_n - m * m;
        MEAN[c] = (float)m;
        RSTD[c] = rsqrtf((float)var + 1e-5f);
    }
}

// ---------------- LIF layer 1 -> spike bitmask (UNCHANGED) -----------------
__global__ __launch_bounds__(256)
void lif1_kernel(const float* __restrict__ gamma, const float* __restrict__ beta)
{
    size_t tid = (size_t)blockIdx.x * blockDim.x + threadIdx.x;
    int c = (int)(tid % HDIM);
    size_t rest = tid / HDIM;
    int n = (int)(rest % NSEQ);
    int b = (int)(rest / NSEQ);

    float m  = g_mean1[c];
    float r  = g_rstd1[c];
    float gm = gamma[c];
    float bt = beta[c];

    int f = n * HDIM + c;
    int k = f / NSEQ;
    int j = f - k * NSEQ;
    uint32_t bit  = 1u << (k & 31);
    int      word = k >> 5;

    float v = 0.f;
#pragma unroll
    for (int t = 0; t < TSTEP; t++) {
        int tb = t * BB + b;
        float x  = g_h1[((size_t)tb * NSEQ + n) * HDIM + c];
        float xn = __fadd_rn(__fmul_rn(__fmul_rn(gm, __fsub_rn(x, m)), r), bt);
        v = __fadd_rn(v, __fmul_rn(__fsub_rn(xn, v), 0.5f));
        if (v >= 1.0f) {
            atomicOr(&g_mask[(size_t)(tb * NSEQ + j) * NWORD + word], bit);
            v = 0.f;
        }
    }
}

// ---------------- sparse GEMM2: 8 rows in parallel, ILP-8 chains -----------
// o2[r][c] = sum_{k active, ascending} w2T[k][c]  (exact FADD chain per (r,c)).
// Thread (r = tid>>6, c0 = (tid&63)*8) owns 8 channels of one row:
// 8 independent chains + 4-k load batching -> MLP 8.
#define RPC 8
__global__ __launch_bounds__(512)
void gemm2_sparse_kernel()
{
    __shared__ uint16_t klist[RPC][HDIM];
    __shared__ int wsum[16];
    __shared__ int knum[RPC];

    const int tid = threadIdx.x;
    const int r   = tid >> 6;          // row slot 0..7
    const int w   = tid & 63;          // mask word
    const int row = blockIdx.x * RPC + r;

    // ---- scan + decode (thread owns word w of row r) ----
    uint32_t mw = g_mask[(size_t)row * NWORD + w];
    int cnt = __popc(mw);
    int incl = cnt;
#pragma unroll
    for (int d = 1; d < 32; d <<= 1) {
        int vv = __shfl_up_sync(0xffffffffu, incl, d);
        if ((tid & 31) >= d) incl += vv;
    }
    if ((tid & 31) == 31) wsum[tid >> 5] = incl;
    __syncthreads();

    int off = incl - cnt + ((w >= 32) ? wsum[r * 2] : 0);
    {
        uint32_t m2 = mw;
        int kb = w * 32;
        while (m2) {
            int b = __ffs(m2) - 1;
            m2 &= m2 - 1;
            klist[r][off++] = (uint16_t)(kb + b);
        }
    }
    if (w == 0) knum[r] = wsum[r * 2] + wsum[r * 2 + 1];
    __syncthreads();

    // ---- accumulate: 8 channels per thread, ascending-k FADD chains ----
    const int c0 = (tid & 63) * 8;
    const int kn = knum[r];
    float acc[8];
#pragma unroll
    for (int j = 0; j < 8; j++) acc[j] = 0.f;

    int i = 0;
    for (; i + 4 <= kn; i += 4) {
        int k0 = klist[r][i+0], k1 = klist[r][i+1];
        int k2 = klist[r][i+2], k3 = klist[r][i+3];
        const float4* p0 = (const float4*)(g_w2T + (size_t)k0 * CDIM + c0);
        const float4* p1 = (const float4*)(g_w2T + (size_t)k1 * CDIM + c0);
        const float4* p2 = (const float4*)(g_w2T + (size_t)k2 * CDIM + c0);
        const float4* p3 = (const float4*)(g_w2T + (size_t)k3 * CDIM + c0);
        float4 a0 = p0[0], a1 = p0[1];
        float4 b0 = p1[0], b1 = p1[1];
        float4 c0_ = p2[0], c1_ = p2[1];
        float4 d0 = p3[0], d1 = p3[1];
        // k0
        acc[0] = __fadd_rn(acc[0], a0.x); acc[1] = __fadd_rn(acc[1], a0.y);
        acc[2] = __fadd_rn(acc[2], a0.z); acc[3] = __fadd_rn(acc[3], a0.w);
        acc[4] = __fadd_rn(acc[4], a1.x); acc[5] = __fadd_rn(acc[5], a1.y);
        acc[6] = __fadd_rn(acc[6], a1.z); acc[7] = __fadd_rn(acc[7], a1.w);
        // k1
        acc[0] = __fadd_rn(acc[0], b0.x); acc[1] = __fadd_rn(acc[1], b0.y);
        acc[2] = __fadd_rn(acc[2], b0.z); acc[3] = __fadd_rn(acc[3], b0.w);
        acc[4] = __fadd_rn(acc[4], b1.x); acc[5] = __fadd_rn(acc[5], b1.y);
        acc[6] = __fadd_rn(acc[6], b1.z); acc[7] = __fadd_rn(acc[7], b1.w);
        // k2
        acc[0] = __fadd_rn(acc[0], c0_.x); acc[1] = __fadd_rn(acc[1], c0_.y);
        acc[2] = __fadd_rn(acc[2], c0_.z); acc[3] = __fadd_rn(acc[3], c0_.w);
        acc[4] = __fadd_rn(acc[4], c1_.x); acc[5] = __fadd_rn(acc[5], c1_.y);
        acc[6] = __fadd_rn(acc[6], c1_.z); acc[7] = __fadd_rn(acc[7], c1_.w);
        // k3
        acc[0] = __fadd_rn(acc[0], d0.x); acc[1] = __fadd_rn(acc[1], d0.y);
        acc[2] = __fadd_rn(acc[2], d0.z); acc[3] = __fadd_rn(acc[3], d0.w);
        acc[4] = __fadd_rn(acc[4], d1.x); acc[5] = __fadd_rn(acc[5], d1.y);
        acc[6] = __fadd_rn(acc[6], d1.z); acc[7] = __fadd_rn(acc[7], d1.w);
    }
    for (; i < kn; i++) {
        int k = klist[r][i];
        const float4* p = (const float4*)(g_w2T + (size_t)k * CDIM + c0);
        float4 v0 = p[0], v1 = p[1];
        acc[0] = __fadd_rn(acc[0], v0.x); acc[1] = __fadd_rn(acc[1], v0.y);
        acc[2] = __fadd_rn(acc[2], v0.z); acc[3] = __fadd_rn(acc[3], v0.w);
        acc[4] = __fadd_rn(acc[4], v1.x); acc[5] = __fadd_rn(acc[5], v1.y);
        acc[6] = __fadd_rn(acc[6], v1.z); acc[7] = __fadd_rn(acc[7], v1.w);
    }

    float* op = g_o2 + (size_t)row * CDIM + c0;
    *(float4*)(op)     = make_float4(acc[0], acc[1], acc[2], acc[3]);
    *(float4*)(op + 4) = make_float4(acc[4], acc[5], acc[6], acc[7]);
}

// ---------------- LIF layer 2 (UNCHANGED) ----------------------------------
__global__ __launch_bounds__(256)
void lif2_kernel(const float* __restrict__ gamma, const float* __restrict__ beta)
{
    size_t tid = (size_t)blockIdx.x * blockDim.x + threadIdx.x;
    int c = (int)(tid % CDIM);
    size_t rest = tid / CDIM;
    int n = (int)(rest % NSEQ);
    int b = (int)(rest / NSEQ);

    float m  = g_mean2[c];
    float r  = g_rstd2[c];
    float gm = gamma[c];
    float bt = beta[c];

    float v = 0.f;
#pragma unroll
    for (int t = 0; t < TSTEP; t++) {
        size_t tb = (size_t)(t * BB + b);
        float x  = g_o2[(tb * NSEQ + n) * CDIM + c];
        float xn = __fadd_rn(__fmul_rn(__fmul_rn(gm, __fsub_rn(x, m)), r), bt);
        v = __fadd_rn(v, __fmul_rn(__fsub_rn(xn, v), 0.5f));
        float sp = (v >= 1.0f) ? 1.0f : 0.0f;
        g_s2[tb * SLAB2 + (size_t)n * CDIM + c] = sp;
        if (v >= 1.0f) v = 0.f;
    }
}

// ---------------- final permuted write -------------------------------------
__global__ void transpose_out_kernel(float* __restrict__ out)
{
    __shared__ float tile[32][33];
    int tb = blockIdx.z;
    int i0 = blockIdx.y * 32;
    int j0 = blockIdx.x * 32;
    const float* src = g_s2 + (size_t)tb * SLAB2;
    float* dst = out + (size_t)tb * SLAB2;
    int x = threadIdx.x, y = threadIdx.y;

#pragma unroll
    for (int yy = y; yy < 32; yy += 8) {
        int i = i0 + yy, j = j0 + x;
        if (j < NSEQ) tile[yy][x] = src[(size_t)i * NSEQ + j];
    }
    __syncthreads();
#pragma unroll
    for (int yy = y; yy < 32; yy += 8) {
        int j = j0 + yy, i = i0 + x;
        if (j < NSEQ) dst[(size_t)j * CDIM + i] = tile[x][yy];
    }
}

// ---------------- launch ----------------------------------------------------
extern "C" void kernel_launch(void* const* d_in, const int* in_sizes, int n_in,
                              void* d_out, int out_size)
{
    const float* x  = (const float*)d_in[0];
    const float* w1 = (const float*)d_in[1];
    const float* g1 = (const float*)d_in[2];
    const float* b1 = (const float*)d_in[3];
    const float* w2 = (const float*)d_in[4];
    const float* g2 = (const float*)d_in[5];
    const float* b2 = (const float*)d_in[6];
    float* out = (float*)d_out;

    float *p_xT, *p_w1T, *p_w2T;
    cudaGetSymbolAddress((void**)&p_xT,  g_xT);
    cudaGetSymbolAddress((void**)&p_w1T, g_w1T);
    cudaGetSymbolAddress((void**)&p_w2T, g_w2T);

    zero_stats_kernel<<<8, 256>>>();
    zero_mask_kernel<<<((size_t)MROWS * NWORD + 1023) / 1024, 1024>>>();

    transpose_rc_kernel<<<dim3(MROWS / 32, CDIM / 32), dim3(32, 8)>>>(x,  p_xT,  MROWS, CDIM);
    transpose_rc_kernel<<<dim3(HDIM / 32, CDIM / 32), dim3(32, 8)>>>(w1, p_w1T, HDIM, CDIM);
    transpose_rc_kernel<<<dim3(CDIM / 32, HDIM / 32), dim3(32, 8)>>>(w2, p_w2T, CDIM, HDIM);

    // Layer 1: pipelined f32x2 GEMM (bitwise chain) -> g_h1
    sgemm1_kernel<<<dim3(HDIM / BN, MROWS / BM), 256>>>();
    bn_stats_kernel<false><<<MROWS / 128, 256>>>();
    bn_final_kernel<false><<<HDIM / 256, 256>>>();
    lif1_kernel<<<((size_t)BB * NSEQ * HDIM) / 256, 256>>>(g1, b1);

    // Layer 2: row-parallel sparse spike GEMM -> g_o2
    gemm2_sparse_kernel<<<MROWS / RPC, 512>>>();
    bn_stats_kernel<true><<<MROWS / 128, 256>>>();
    bn_final_kernel<true><<<CDIM / 256, 256>>>();
    lif2_kernel<<<((size_t)BB * NSEQ * CDIM) / 256, 256>>>(g2, b2);

    transpose_out_kernel<<<dim3(7, CDIM / 32, TB_), dim3(32, 8)>>>(out);
}